// round 16
// baseline (speedup 1.0000x reference)
#include <cuda_runtime.h>
#include <cuda_bf16.h>
#include <math.h>
#include <stdint.h>

#define BDIM 32
#define L1DIM 128
#define L2DIM 128
#define DDIM 300
#define KDIM 50
#define ROWS1 (BDIM * L1DIM)   // 4096
#define ROWS2 (BDIM * L2DIM)   // 4096
#define NPAD 15104             // 118*128 compact (k*300+e) rows for Wb'
#define TSTRIDE (KDIM * DDIM)  // 15000

// Scratch (__device__ globals; zero-initialized at module load)
__device__ float g_t[(size_t)ROWS1 * TSTRIDE];           // 245.8 MB tf32-rounded t
__device__ float g_btp[(size_t)BDIM * 6400 * 128];       // 104.9 MB
__device__ float g_wbt[(size_t)NPAD * DDIM];             // 18.1 MB tf32 Wb'[(k*300+e)][d]
__device__ float g_e1t[(size_t)ROWS1 * DDIM];            // 4.9 MB tf32 e1
__device__ float g_e2t[(size_t)ROWS2 * DDIM];            // 4.9 MB tf32 e2
__device__ float g_p1d[ROWS1 * KDIM];
__device__ float g_p1g[ROWS1 * KDIM];
__device__ float g_p2d[ROWS2 * KDIM];
__device__ float g_p2g[ROWS2 * KDIM];

// ---------------------------------------------------------------------------
// helpers (plain sm_80+ PTX)
// ---------------------------------------------------------------------------
__device__ __forceinline__ uint32_t smem_u32(const void* p) {
    uint32_t a;
    asm("{ .reg .u64 t; cvta.to.shared.u64 t, %1; cvt.u32.u64 %0, t; }" : "=r"(a) : "l"(p));
    return a;
}
__device__ __forceinline__ void cpasync16z(uint32_t dst, const void* src, int nb) {
    asm volatile("cp.async.cg.shared.global [%0], [%1], 16, %2;"
                 :: "r"(dst), "l"(src), "r"(nb));
}
__device__ __forceinline__ void ldsm_x4(uint32_t& r0, uint32_t& r1, uint32_t& r2,
                                        uint32_t& r3, uint32_t addr) {
    asm volatile("ldmatrix.sync.aligned.m8n8.x4.shared.b16 {%0,%1,%2,%3}, [%4];"
                 : "=r"(r0), "=r"(r1), "=r"(r2), "=r"(r3) : "r"(addr));
}
__device__ __forceinline__ void mma_tf32(float* c, const uint32_t* a, const uint32_t* b) {
    asm volatile(
        "mma.sync.aligned.m16n8k8.row.col.f32.tf32.tf32.f32 "
        "{%0,%1,%2,%3}, {%4,%5,%6,%7}, {%8,%9}, {%0,%1,%2,%3};"
        : "+f"(c[0]), "+f"(c[1]), "+f"(c[2]), "+f"(c[3])
        : "r"(a[0]), "r"(a[1]), "r"(a[2]), "r"(a[3]), "r"(b[0]), "r"(b[1]));
}
__device__ __forceinline__ uint32_t f2tf32(float f) {
    uint32_t r;
    asm("cvt.rna.tf32.f32 %0, %1;" : "=r"(r) : "f"(f));
    return r;
}
__device__ __forceinline__ float tf32r(float f) {
    return __uint_as_float(f2tf32(f));
}
__device__ __forceinline__ float tanh_hw(float x) {
    float y;
    asm("tanh.approx.f32 %0, %1;" : "=f"(y) : "f"(x));
    return y;
}

// ---------------------------------------------------------------------------
// convE: e1/e2 fp32 -> tf32-rounded fp32 copies
// ---------------------------------------------------------------------------
__global__ void convE_kernel(const float* __restrict__ e1,
                             const float* __restrict__ e2) {
    int m = blockIdx.x;                  // 0..8191
    int d = threadIdx.x;                 // 0..319
    if (d >= DDIM) return;
    bool s2 = (m >= ROWS1);
    int row = s2 ? m - ROWS1 : m;
    const float* src = s2 ? e2 : e1;
    float* dst = s2 ? g_e2t : g_e1t;
    dst[(size_t)row * DDIM + d] = tf32r(src[(size_t)row * DDIM + d]);
}

// ---------------------------------------------------------------------------
// convB: Wb[k][d][e] -> tf32-rounded Wb'[(k*300+e)][d]
// ---------------------------------------------------------------------------
__global__ void convB_kernel(const float* __restrict__ Wb) {
    __shared__ float tile[32][33];
    int k  = blockIdx.z;
    int d0 = blockIdx.x * 32;
    int e0 = blockIdx.y * 32;
    int tx = threadIdx.x, ty = threadIdx.y;   // 32 x 8
    #pragma unroll
    for (int q = 0; q < 4; q++) {
        int d = d0 + ty + 8 * q;
        int e = e0 + tx;
        float v = 0.f;
        if (d < DDIM && e < DDIM)
            v = Wb[(size_t)k * DDIM * DDIM + (size_t)d * DDIM + e];
        tile[ty + 8 * q][tx] = v;
    }
    __syncthreads();
    #pragma unroll
    for (int q = 0; q < 4; q++) {
        int e = e0 + ty + 8 * q;
        int d = d0 + tx;
        if (e < DDIM && d < DDIM)
            g_wbt[(size_t)(k * DDIM + e) * DDIM + d] = tf32r(tile[tx][ty + 8 * q]);
    }
}

// ---------------------------------------------------------------------------
// tf32 GEMM core: CTA 128x128, 8 warps 4(m)x2(n) -> warp 32x64, KC=32,
// 3-stage cp.async ring with ONE syncthreads per chunk, fragments via
// ldmatrix.x4. 108 KB smem, 2 CTAs/SM.
// ---------------------------------------------------------------------------
#define BT_THREADS 256
#define BT_KC 32
#define BT_ROWB 144                       // 32 fp32 (128B) + 16B pad
#define BT_TILE (128 * BT_ROWB)           // 18432
#define BT_STAGE (2 * BT_TILE)            // A + B = 36864
#define BT_SMEM (3 * BT_STAGE)            // 110592 (3-stage ring)
#define BT_NCH 10                         // ceil(300/32) (tail zero-filled)

struct Tf32Core {
    uint32_t sb;
    int tid, lane, wm, wn;
    const float *A, *B;
    float acc[2][8][4];

    __device__ __forceinline__ void init(uint32_t sb_, int tid_,
                                         const float* A_, const float* B_) {
        sb = sb_; tid = tid_;
        lane = tid & 31;
        int w = tid >> 5;
        wm = (w >> 1) * 32;               // 0,32,64,96
        wn = (w & 1) * 64;                // 0,64
        A = A_; B = B_;
        #pragma unroll
        for (int mt = 0; mt < 2; mt++)
            #pragma unroll
            for (int nt = 0; nt < 8; nt++)
                #pragma unroll
                for (int q = 0; q < 4; q++) acc[mt][nt][q] = 0.f;
    }

    __device__ __forceinline__ void issue(int c) {
        int d0 = c * BT_KC;
        uint32_t stage = sb + (c % 3) * BT_STAGE;
        #pragma unroll
        for (int it = 0; it < 8; it++) {
            int i = tid + BT_THREADS * it;        // 0..2047
            bool isA = (i < 1024);
            int idx = i & 1023;
            int r = idx >> 3, c4 = idx & 7;       // 128 rows x 8 float4
            int colb = d0 + c4 * 4;
            int nb = (colb + 4 <= DDIM) ? 16 : 0; // K tail: zero-fill
            const float* src = (isA ? A : B) + (size_t)r * DDIM + (nb ? colb : 0);
            uint32_t dst = stage + (isA ? 0 : BT_TILE) + r * BT_ROWB + c4 * 16;
            cpasync16z(dst, src, nb);
        }
        asm volatile("cp.async.commit_group;" ::: "memory");
    }

    __device__ __forceinline__ void compute(int c) {
        uint32_t sA = sb + (c % 3) * BT_STAGE;
        uint32_t sB = sA + BT_TILE;
        #pragma unroll
        for (int kk = 0; kk < BT_KC / 8; kk++) {
            uint32_t afr[2][4];
            #pragma unroll
            for (int mt = 0; mt < 2; mt++) {
                uint32_t aoff = (uint32_t)(wm + mt * 16 + (lane & 15)) * BT_ROWB
                              + kk * 32 + (lane >> 4) * 16;
                ldsm_x4(afr[mt][0], afr[mt][1], afr[mt][2], afr[mt][3], sA + aoff);
            }
            uint32_t bfr[8][2];
            #pragma unroll
            for (int nq = 0; nq < 4; nq++) {
                uint32_t brow = (uint32_t)(wn + nq * 16 + (lane & 7) + ((lane >> 4) << 3));
                uint32_t boff = brow * BT_ROWB + kk * 32 + ((lane >> 3) & 1) * 16;
                ldsm_x4(bfr[2*nq][0], bfr[2*nq][1], bfr[2*nq+1][0], bfr[2*nq+1][1], sB + boff);
            }
            #pragma unroll
            for (int mt = 0; mt < 2; mt++)
                #pragma unroll
                for (int nt = 0; nt < 8; nt++)
                    mma_tf32(acc[mt][nt], afr[mt], bfr[nt]);
        }
    }

    // 3-stage ring: issue(c+2) overwrites stage (c-1)%3 whose readers finished
    // before this iteration's pre-compute sync -> ONE sync per chunk.
    __device__ __forceinline__ void run() {
        issue(0);
        issue(1);
        for (int c = 0; c < BT_NCH; c++) {
            if (c + 1 < BT_NCH) {
                asm volatile("cp.async.wait_group 1;" ::: "memory");
            } else {
                asm volatile("cp.async.wait_group 0;" ::: "memory");
            }
            __syncthreads();
            compute(c);
            if (c + 2 < BT_NCH) issue(c + 2);
        }
    }
};

// ---------------------------------------------------------------------------
// Stage-1 (tf32): t[4096 x 15000] = e1t[4096 x 300] @ Wb'[15104 x 300]^T
// ---------------------------------------------------------------------------
__global__ __launch_bounds__(BT_THREADS, 2)
void tmat_tf32_kernel() {
    extern __shared__ char smem[];
    Tf32Core g;
    int m0 = blockIdx.x * 128;            // in 4096
    int n0 = blockIdx.y * 128;            // in 15104
    g.init(smem_u32(smem), threadIdx.x,
           g_e1t + (size_t)m0 * DDIM,
           g_wbt + (size_t)n0 * DDIM);
    g.run();

    #pragma unroll
    for (int mt = 0; mt < 2; mt++) {
        int row = m0 + g.wm + mt * 16 + (g.lane >> 2);
        float* r0p = g_t + (size_t)row * TSTRIDE;
        float* r1p = r0p + (size_t)8 * TSTRIDE;
        #pragma unroll
        for (int nt = 0; nt < 8; nt++) {
            int col = n0 + g.wn + nt * 8 + 2 * (g.lane & 3);
            if (col < TSTRIDE) {
                *reinterpret_cast<float2*>(r0p + col) =
                    make_float2(tf32r(g.acc[mt][nt][0]), tf32r(g.acc[mt][nt][1]));
                *reinterpret_cast<float2*>(r1p + col) =
                    make_float2(tf32r(g.acc[mt][nt][2]), tf32r(g.acc[mt][nt][3]));
            }
        }
    }
}

// ---------------------------------------------------------------------------
// Stage-2 (tf32, per b): btp[6400 x 128] = T_b[6400 x 300] @ e2t_b[128 x 300]^T
// ---------------------------------------------------------------------------
__global__ __launch_bounds__(BT_THREADS, 2)
void btp_tf32_kernel() {
    extern __shared__ char smem[];
    Tf32Core g;
    int m0 = blockIdx.x * 128;            // in 6400
    int b  = blockIdx.y;
    g.init(smem_u32(smem), threadIdx.x,
           g_t + (size_t)b * 6400 * DDIM + (size_t)m0 * DDIM,
           g_e2t + (size_t)b * 128 * DDIM);
    g.run();

    float* dst = g_btp + (size_t)b * 6400 * 128;
    #pragma unroll
    for (int mt = 0; mt < 2; mt++) {
        int row = m0 + g.wm + mt * 16 + (g.lane >> 2);
        float* r0p = dst + (size_t)row * 128 + g.wn;
        float* r1p = r0p + 8 * 128;
        #pragma unroll
        for (int nt = 0; nt < 8; nt++) {
            int coff = nt * 8 + 2 * (g.lane & 3);
            *reinterpret_cast<float2*>(r0p + coff) = make_float2(g.acc[mt][nt][0], g.acc[mt][nt][1]);
            *reinterpret_cast<float2*>(r1p + coff) = make_float2(g.acc[mt][nt][2], g.acc[mt][nt][3]);
        }
    }
}

// ---------------------------------------------------------------------------
// gate epilogue v2 (2 MUFU/element):
//   g = 0.5 + 0.5*tanh(sg/2)  (== sigmoid(sg), one MUFU instead of EX2+RCP)
//   out[b,i,j] = sum_k u_k*( sln + g*(btp - sln) ) + sum_k u_k*bb_k
// p1g'/p2g' pre-halved at staging; u.bb folded out of the k-loop.
// ---------------------------------------------------------------------------
#define G_P2LD 129
#define G_SMEM ((2 * KDIM * G_P2LD + 4 * 64) * 4)

__global__ __launch_bounds__(128)
void gate_kernel(const float* __restrict__ bg,
                 const float* __restrict__ bb,
                 const float* __restrict__ u,
                 float* __restrict__ out) {
    extern __shared__ float sm[];
    float* p2dS  = sm;                    // [50][129]
    float* p2g2S = sm + KDIM * G_P2LD;    // [50][129] (pre-halved)
    float* p1dS  = p2g2S + KDIM * G_P2LD; // [64]
    float* p1g2S = p1dS + 64;             // [64] (pre-halved, +bg/2)
    float* uS    = p1g2S + 64;
    float* ubbS  = uS + 64;               // [1] broadcast of sum u*bb

    int blk = blockIdx.x;                 // b*128 + i
    int b   = blk >> 7;
    int tid = threadIdx.x;                // j

    const float* p2d_b = g_p2d + (size_t)b * 128 * KDIM;
    const float* p2g_b = g_p2g + (size_t)b * 128 * KDIM;
    for (int idx = tid; idx < 128 * KDIM; idx += 128) {
        int j = idx / KDIM, k = idx - j * KDIM;
        p2dS[k * G_P2LD + j]  = p2d_b[idx];
        p2g2S[k * G_P2LD + j] = 0.5f * p2g_b[idx];
    }
    if (tid < KDIM) {
        p1dS[tid]  = g_p1d[(size_t)blk * KDIM + tid];
        p1g2S[tid] = 0.5f * (g_p1g[(size_t)blk * KDIM + tid] + bg[tid]);
        uS[tid]    = u[tid];
    }
    if (tid == 0) {
        float s = 0.f;
        for (int k = 0; k < KDIM; k++) s += u[k] * bb[k];
        ubbS[0] = s;
    }
    __syncthreads();

    const float* btp_row = g_btp + (size_t)b * 6400 * 128 + (size_t)(blk & 127) * KDIM * 128;

    float acc = ubbS[0];
    #pragma unroll 5
    for (int k = 0; k < KDIM; k++) {
        float btp = btp_row[k * 128 + tid];
        float sln = tanh_hw(p1dS[k] + p2dS[k * G_P2LD + tid]);
        float g   = fmaf(tanh_hw(p1g2S[k] + p2g2S[k * G_P2LD + tid]), 0.5f, 0.5f);
        float mix = fmaf(g, btp - sln, sln);
        acc = fmaf(uS[k], mix, acc);
    }
    out[(size_t)blk * 128 + tid] = acc;
}

// ---------------------------------------------------------------------------
// projections: warp = one 4-row group, lanes = consecutive k.
// ---------------------------------------------------------------------------
#define P_ROWS 32
#define P_THREADS 512
#define P_SMEM ((DDIM * KDIM + DDIM * P_ROWS) * 4)

__global__ __launch_bounds__(P_THREADS)
void proj_kernel(const float* __restrict__ e1,
                 const float* __restrict__ e2,
                 const float* __restrict__ Wd,
                 const float* __restrict__ Wg) {
    extern __shared__ float sm[];
    float* WS   = sm;                    // [300][50]
    float* rowS = sm + DDIM * KDIM;      // [300][32]

    int blk = blockIdx.x;
    int rt  = blk & 127;
    int mt  = (blk >> 7) & 1;
    int s   = blk >> 8;
    int row0 = rt * P_ROWS;
    int tid = threadIdx.x;

    const float* E = s ? e2 : e1;
    const float* W = (mt ? Wg : Wd) + s * DDIM * KDIM;
    float* out = s ? (mt ? g_p2g : g_p2d) : (mt ? g_p1g : g_p1d);

    const float4* W4 = reinterpret_cast<const float4*>(W);
    float4* WS4 = reinterpret_cast<float4*>(WS);
    for (int i = tid; i < DDIM * KDIM / 4; i += P_THREADS) WS4[i] = W4[i];

    for (int i = tid; i < P_ROWS * (DDIM / 4); i += P_THREADS) {
        int r = i / (DDIM / 4);
        int c4 = i % (DDIM / 4);
        float4 v = *reinterpret_cast<const float4*>(&E[(size_t)(row0 + r) * DDIM + 4 * c4]);
        rowS[(4 * c4 + 0) * P_ROWS + r] = v.x;
        rowS[(4 * c4 + 1) * P_ROWS + r] = v.y;
        rowS[(4 * c4 + 2) * P_ROWS + r] = v.z;
        rowS[(4 * c4 + 3) * P_ROWS + r] = v.w;
    }
    __syncthreads();

    int k  = tid & 63;
    int r4 = tid >> 6;                   // 0..7
    if (k < KDIM) {
        float4 acc = make_float4(0.f, 0.f, 0.f, 0.f);
        #pragma unroll 4
        for (int d = 0; d < DDIM; d++) {
            float4 x = *reinterpret_cast<const float4*>(&rowS[d * P_ROWS + r4 * 4]);
            float w = WS[d * KDIM + k];
            acc.x = fmaf(x.x, w, acc.x);
            acc.y = fmaf(x.y, w, acc.y);
            acc.z = fmaf(x.z, w, acc.z);
            acc.w = fmaf(x.w, w, acc.w);
        }
        int rb = row0 + r4 * 4;
        out[(size_t)(rb + 0) * KDIM + k] = acc.x;
        out[(size_t)(rb + 1) * KDIM + k] = acc.y;
        out[(size_t)(rb + 2) * KDIM + k] = acc.z;
        out[(size_t)(rb + 3) * KDIM + k] = acc.w;
    }
}

// ---------------------------------------------------------------------------
extern "C" void kernel_launch(void* const* d_in, const int* in_sizes, int n_in,
                              void* d_out, int out_size) {
    const float* e1 = (const float*)d_in[0];
    const float* e2 = (const float*)d_in[1];
    const float* Wb = (const float*)d_in[2];
    const float* Wd = (const float*)d_in[3];
    const float* Wg = (const float*)d_in[4];
    const float* bg = (const float*)d_in[5];
    const float* bb = (const float*)d_in[6];
    const float* u  = (const float*)d_in[7];
    float* out = (float*)d_out;

    cudaFuncSetAttribute(proj_kernel, cudaFuncAttributeMaxDynamicSharedMemorySize, P_SMEM);
    cudaFuncSetAttribute(tmat_tf32_kernel, cudaFuncAttributeMaxDynamicSharedMemorySize, BT_SMEM);
    cudaFuncSetAttribute(btp_tf32_kernel, cudaFuncAttributeMaxDynamicSharedMemorySize, BT_SMEM);
    cudaFuncSetAttribute(gate_kernel, cudaFuncAttributeMaxDynamicSharedMemorySize, G_SMEM);

    convE_kernel<<<2 * ROWS1, 320>>>(e1, e2);
    convB_kernel<<<dim3(10, 10, KDIM), dim3(32, 8)>>>(Wb);
    proj_kernel<<<512, P_THREADS, P_SMEM>>>(e1, e2, Wd, Wg);
    tmat_tf32_kernel<<<dim3(ROWS1 / 128, NPAD / 128), BT_THREADS, BT_SMEM>>>();
    btp_tf32_kernel<<<dim3(6400 / 128, BDIM), BT_THREADS, BT_SMEM>>>();
    gate_kernel<<<ROWS1, 128, G_SMEM>>>(bg, bb, u, out);
}

// round 17
// speedup vs baseline: 1.1031x; 1.1031x over previous
#include <cuda_runtime.h>
#include <cuda_bf16.h>
#include <math.h>
#include <stdint.h>

#define BDIM 32
#define L1DIM 128
#define L2DIM 128
#define DDIM 300
#define KDIM 50
#define ROWS1 (BDIM * L1DIM)   // 4096
#define ROWS2 (BDIM * L2DIM)   // 4096
#define NPAD 15104             // 118*128 compact (k*300+e) rows for Wb'
#define TSTRIDE (KDIM * DDIM)  // 15000

// Scratch (__device__ globals; zero-initialized at module load)
__device__ float g_t[(size_t)ROWS1 * TSTRIDE];           // 245.8 MB tf32-rounded t
__device__ float g_wbt[(size_t)NPAD * DDIM];             // 18.1 MB tf32 Wb'[(k*300+e)][d]
__device__ float g_e1t[(size_t)ROWS1 * DDIM];            // 4.9 MB tf32 e1
__device__ float g_e2t[(size_t)ROWS2 * DDIM];            // 4.9 MB tf32 e2
__device__ float g_p1d[ROWS1 * KDIM];
__device__ float g_p1g[ROWS1 * KDIM];
__device__ float g_p2d[ROWS2 * KDIM];
__device__ float g_p2g[ROWS2 * KDIM];

// ---------------------------------------------------------------------------
// helpers (plain sm_80+ PTX)
// ---------------------------------------------------------------------------
__device__ __forceinline__ uint32_t smem_u32(const void* p) {
    uint32_t a;
    asm("{ .reg .u64 t; cvta.to.shared.u64 t, %1; cvt.u32.u64 %0, t; }" : "=r"(a) : "l"(p));
    return a;
}
__device__ __forceinline__ void cpasync16z(uint32_t dst, const void* src, int nb) {
    asm volatile("cp.async.cg.shared.global [%0], [%1], 16, %2;"
                 :: "r"(dst), "l"(src), "r"(nb));
}
__device__ __forceinline__ void ldsm_x4(uint32_t& r0, uint32_t& r1, uint32_t& r2,
                                        uint32_t& r3, uint32_t addr) {
    asm volatile("ldmatrix.sync.aligned.m8n8.x4.shared.b16 {%0,%1,%2,%3}, [%4];"
                 : "=r"(r0), "=r"(r1), "=r"(r2), "=r"(r3) : "r"(addr));
}
__device__ __forceinline__ void mma_tf32(float* c, const uint32_t* a, const uint32_t* b) {
    asm volatile(
        "mma.sync.aligned.m16n8k8.row.col.f32.tf32.tf32.f32 "
        "{%0,%1,%2,%3}, {%4,%5,%6,%7}, {%8,%9}, {%0,%1,%2,%3};"
        : "+f"(c[0]), "+f"(c[1]), "+f"(c[2]), "+f"(c[3])
        : "r"(a[0]), "r"(a[1]), "r"(a[2]), "r"(a[3]), "r"(b[0]), "r"(b[1]));
}
__device__ __forceinline__ uint32_t f2tf32(float f) {
    uint32_t r;
    asm("cvt.rna.tf32.f32 %0, %1;" : "=r"(r) : "f"(f));
    return r;
}
__device__ __forceinline__ float tf32r(float f) {
    return __uint_as_float(f2tf32(f));
}
__device__ __forceinline__ float tanh_hw(float x) {
    float y;
    asm("tanh.approx.f32 %0, %1;" : "=f"(y) : "f"(x));
    return y;
}

// ---------------------------------------------------------------------------
// convE: e1/e2 fp32 -> tf32-rounded fp32 copies
// ---------------------------------------------------------------------------
__global__ void convE_kernel(const float* __restrict__ e1,
                             const float* __restrict__ e2) {
    int m = blockIdx.x;                  // 0..8191
    int d = threadIdx.x;                 // 0..319
    if (d >= DDIM) return;
    bool s2 = (m >= ROWS1);
    int row = s2 ? m - ROWS1 : m;
    const float* src = s2 ? e2 : e1;
    float* dst = s2 ? g_e2t : g_e1t;
    dst[(size_t)row * DDIM + d] = tf32r(src[(size_t)row * DDIM + d]);
}

// ---------------------------------------------------------------------------
// convB: Wb[k][d][e] -> tf32-rounded Wb'[(k*300+e)][d]
// ---------------------------------------------------------------------------
__global__ void convB_kernel(const float* __restrict__ Wb) {
    __shared__ float tile[32][33];
    int k  = blockIdx.z;
    int d0 = blockIdx.x * 32;
    int e0 = blockIdx.y * 32;
    int tx = threadIdx.x, ty = threadIdx.y;   // 32 x 8
    #pragma unroll
    for (int q = 0; q < 4; q++) {
        int d = d0 + ty + 8 * q;
        int e = e0 + tx;
        float v = 0.f;
        if (d < DDIM && e < DDIM)
            v = Wb[(size_t)k * DDIM * DDIM + (size_t)d * DDIM + e];
        tile[ty + 8 * q][tx] = v;
    }
    __syncthreads();
    #pragma unroll
    for (int q = 0; q < 4; q++) {
        int e = e0 + ty + 8 * q;
        int d = d0 + tx;
        if (e < DDIM && d < DDIM)
            g_wbt[(size_t)(k * DDIM + e) * DDIM + d] = tf32r(tile[tx][ty + 8 * q]);
    }
}

// ---------------------------------------------------------------------------
// tf32 GEMM core: CTA 128x128, 8 warps 4(m)x2(n) -> warp 32x64, KC=32,
// 3-stage cp.async ring with ONE syncthreads per chunk, ldmatrix fragments.
// 108 KB smem, 2 CTAs/SM. arows guards partial A tiles (row zero-fill).
// ---------------------------------------------------------------------------
#define BT_THREADS 256
#define BT_KC 32
#define BT_ROWB 144                       // 32 fp32 (128B) + 16B pad
#define BT_TILE (128 * BT_ROWB)           // 18432
#define BT_STAGE (2 * BT_TILE)            // A + B = 36864
#define BT_SMEM (3 * BT_STAGE)            // 110592 (3-stage ring)
#define BT_NCH 10                         // ceil(300/32) (tail zero-filled)

struct Tf32Core {
    uint32_t sb;
    int tid, lane, wm, wn, arows;
    const float *A, *B;
    float acc[2][8][4];

    __device__ __forceinline__ void init(uint32_t sb_, int tid_,
                                         const float* A_, const float* B_,
                                         int arows_) {
        sb = sb_; tid = tid_;
        lane = tid & 31;
        int w = tid >> 5;
        wm = (w >> 1) * 32;               // 0,32,64,96
        wn = (w & 1) * 64;                // 0,64
        A = A_; B = B_; arows = arows_;
        #pragma unroll
        for (int mt = 0; mt < 2; mt++)
            #pragma unroll
            for (int nt = 0; nt < 8; nt++)
                #pragma unroll
                for (int q = 0; q < 4; q++) acc[mt][nt][q] = 0.f;
    }

    __device__ __forceinline__ void issue(int c) {
        int d0 = c * BT_KC;
        uint32_t stage = sb + (c % 3) * BT_STAGE;
        #pragma unroll
        for (int it = 0; it < 8; it++) {
            int i = tid + BT_THREADS * it;        // 0..2047
            bool isA = (i < 1024);
            int idx = i & 1023;
            int r = idx >> 3, c4 = idx & 7;       // 128 rows x 8 float4
            int colb = d0 + c4 * 4;
            bool ok = (colb + 4 <= DDIM) && (!isA || r < arows);
            int nb = ok ? 16 : 0;
            const float* src = (isA ? A : B) + (ok ? ((size_t)r * DDIM + colb) : 0);
            uint32_t dst = stage + (isA ? 0 : BT_TILE) + r * BT_ROWB + c4 * 16;
            cpasync16z(dst, src, nb);
        }
        asm volatile("cp.async.commit_group;" ::: "memory");
    }

    __device__ __forceinline__ void compute(int c) {
        uint32_t sA = sb + (c % 3) * BT_STAGE;
        uint32_t sB = sA + BT_TILE;
        #pragma unroll
        for (int kk = 0; kk < BT_KC / 8; kk++) {
            uint32_t afr[2][4];
            #pragma unroll
            for (int mt = 0; mt < 2; mt++) {
                uint32_t aoff = (uint32_t)(wm + mt * 16 + (lane & 15)) * BT_ROWB
                              + kk * 32 + (lane >> 4) * 16;
                ldsm_x4(afr[mt][0], afr[mt][1], afr[mt][2], afr[mt][3], sA + aoff);
            }
            uint32_t bfr[8][2];
            #pragma unroll
            for (int nq = 0; nq < 4; nq++) {
                uint32_t brow = (uint32_t)(wn + nq * 16 + (lane & 7) + ((lane >> 4) << 3));
                uint32_t boff = brow * BT_ROWB + kk * 32 + ((lane >> 3) & 1) * 16;
                ldsm_x4(bfr[2*nq][0], bfr[2*nq][1], bfr[2*nq+1][0], bfr[2*nq+1][1], sB + boff);
            }
            #pragma unroll
            for (int mt = 0; mt < 2; mt++)
                #pragma unroll
                for (int nt = 0; nt < 8; nt++)
                    mma_tf32(acc[mt][nt], afr[mt], bfr[nt]);
        }
    }

    __device__ __forceinline__ void run() {
        issue(0);
        issue(1);
        for (int c = 0; c < BT_NCH; c++) {
            if (c + 1 < BT_NCH) {
                asm volatile("cp.async.wait_group 1;" ::: "memory");
            } else {
                asm volatile("cp.async.wait_group 0;" ::: "memory");
            }
            __syncthreads();
            compute(c);
            if (c + 2 < BT_NCH) issue(c + 2);
        }
    }
};

// ---------------------------------------------------------------------------
// Stage-1 (tf32): t[4096 x 15000] = e1t[4096 x 300] @ Wb'[15104 x 300]^T
// ---------------------------------------------------------------------------
__global__ __launch_bounds__(BT_THREADS, 2)
void tmat_tf32_kernel() {
    extern __shared__ char smem[];
    Tf32Core g;
    int m0 = blockIdx.x * 128;            // in 4096
    int n0 = blockIdx.y * 128;            // in 15104
    g.init(smem_u32(smem), threadIdx.x,
           g_e1t + (size_t)m0 * DDIM,
           g_wbt + (size_t)n0 * DDIM, 128);
    g.run();

    #pragma unroll
    for (int mt = 0; mt < 2; mt++) {
        int row = m0 + g.wm + mt * 16 + (g.lane >> 2);
        float* r0p = g_t + (size_t)row * TSTRIDE;
        float* r1p = r0p + (size_t)8 * TSTRIDE;
        #pragma unroll
        for (int nt = 0; nt < 8; nt++) {
            int col = n0 + g.wn + nt * 8 + 2 * (g.lane & 3);
            if (col < TSTRIDE) {
                *reinterpret_cast<float2*>(r0p + col) =
                    make_float2(tf32r(g.acc[mt][nt][0]), tf32r(g.acc[mt][nt][1]));
                *reinterpret_cast<float2*>(r1p + col) =
                    make_float2(tf32r(g.acc[mt][nt][2]), tf32r(g.acc[mt][nt][3]));
            }
        }
    }
}

// ---------------------------------------------------------------------------
// Stage-2 FUSED (tf32 GEMM + gate + u-reduction), per (i-pair, b):
//   CTA tile = 100 valid rows (2 complete i-groups) x 128 cols (all j).
//   btp stays in registers; gate applied in epilogue; smem column-reduce
//   over k emits out[b, i, j] directly. No g_btp, no gate kernel, no atomics.
// ---------------------------------------------------------------------------
#define MIX_LD 130
#define P2_LD 129

__global__ __launch_bounds__(BT_THREADS, 2)
void btp_gate_kernel(const float* __restrict__ bg,
                     const float* __restrict__ bb,
                     const float* __restrict__ u,
                     float* __restrict__ out) {
    extern __shared__ char smem[];
    Tf32Core g;
    int it = blockIdx.x;                  // 0..63 (i-pair tile)
    int b  = blockIdx.y;
    int m0 = it * 100;                    // row offset in 6400
    int arows = (6400 - m0 < 128) ? (6400 - m0) : 128;
    g.init(smem_u32(smem), threadIdx.x,
           g_t + ((size_t)b * 6400 + m0) * DDIM,
           g_e2t + (size_t)b * 128 * DDIM, arows);
    g.run();
    __syncthreads();                      // mainloop smem reads done; reuse ring

    // epilogue smem layout (floats): mix[100][130], p2d[50][129], p2g2[50][129],
    // p1d2[2*64], p1g2[2*64], u[64], ubb[1]  -> 104.9 KB <= 108 KB ring
    float* sm     = reinterpret_cast<float*>(smem);
    float* mixS   = sm;
    float* p2dS   = sm + 100 * MIX_LD;            // 13000
    float* p2g2S  = p2dS + KDIM * P2_LD;          // +6450
    float* p1dS2  = p2g2S + KDIM * P2_LD;         // +6450
    float* p1g2S2 = p1dS2 + 128;
    float* uS     = p1g2S2 + 128;
    float* ubbS   = uS + 64;

    int tid = threadIdx.x;
    int i0  = it * 2;

    const float* p2d_b = g_p2d + (size_t)b * 128 * KDIM;
    const float* p2g_b = g_p2g + (size_t)b * 128 * KDIM;
    for (int idx = tid; idx < 128 * KDIM; idx += BT_THREADS) {
        int j = idx / KDIM, k = idx - j * KDIM;
        p2dS[k * P2_LD + j]  = p2d_b[idx];
        p2g2S[k * P2_LD + j] = 0.5f * p2g_b[idx];
    }
    if (tid < 2 * KDIM) {
        int il = tid / KDIM, k = tid - il * KDIM;
        int blk = b * 128 + i0 + il;
        p1dS2[il * 64 + k]  = g_p1d[(size_t)blk * KDIM + k];
        p1g2S2[il * 64 + k] = 0.5f * (g_p1g[(size_t)blk * KDIM + k] + bg[k]);
    }
    if (tid < KDIM) uS[tid] = u[tid];
    if (tid == 0) {
        float s = 0.f;
        for (int k = 0; k < KDIM; k++) s += u[k] * bb[k];
        ubbS[0] = s;
    }
    __syncthreads();

    // gate math on in-register btp, store mix to smem (valid rows < 100)
    #pragma unroll
    for (int mt = 0; mt < 2; mt++) {
        #pragma unroll
        for (int rr = 0; rr < 2; rr++) {
            int row = g.wm + mt * 16 + (g.lane >> 2) + rr * 8;
            if (row < 100) {
                int il = (row >= 50);
                int k  = row - il * 50;
                float p1d  = p1dS2[il * 64 + k];
                float p1g2 = p1g2S2[il * 64 + k];
                #pragma unroll
                for (int nt = 0; nt < 8; nt++) {
                    int col = g.wn + nt * 8 + 2 * (g.lane & 3);
                    float c0 = g.acc[mt][nt][2 * rr];
                    float c1 = g.acc[mt][nt][2 * rr + 1];
                    float sln0 = tanh_hw(p1d + p2dS[k * P2_LD + col]);
                    float sln1 = tanh_hw(p1d + p2dS[k * P2_LD + col + 1]);
                    float g0 = fmaf(tanh_hw(p1g2 + p2g2S[k * P2_LD + col]), 0.5f, 0.5f);
                    float g1 = fmaf(tanh_hw(p1g2 + p2g2S[k * P2_LD + col + 1]), 0.5f, 0.5f);
                    float mv0 = fmaf(g0, c0 - sln0, sln0);
                    float mv1 = fmaf(g1, c1 - sln1, sln1);
                    *reinterpret_cast<float2*>(&mixS[row * MIX_LD + col]) =
                        make_float2(mv0, mv1);
                }
            }
        }
    }
    __syncthreads();

    // column reduction: thread -> (il, j); k ascending (matches gate kernel order)
    {
        int il = tid >> 7;                // 0..1
        int j  = tid & 127;
        float acc = ubbS[0];
        #pragma unroll 10
        for (int k = 0; k < KDIM; k++)
            acc = fmaf(uS[k], mixS[(il * 50 + k) * MIX_LD + j], acc);
        out[(size_t)(b * 128 + i0 + il) * 128 + j] = acc;
    }
}

// ---------------------------------------------------------------------------
// projections: warp = one 4-row group, lanes = consecutive k.
// ---------------------------------------------------------------------------
#define P_ROWS 32
#define P_THREADS 512
#define P_SMEM ((DDIM * KDIM + DDIM * P_ROWS) * 4)

__global__ __launch_bounds__(P_THREADS)
void proj_kernel(const float* __restrict__ e1,
                 const float* __restrict__ e2,
                 const float* __restrict__ Wd,
                 const float* __restrict__ Wg) {
    extern __shared__ float sm[];
    float* WS   = sm;                    // [300][50]
    float* rowS = sm + DDIM * KDIM;      // [300][32]

    int blk = blockIdx.x;
    int rt  = blk & 127;
    int mt  = (blk >> 7) & 1;
    int s   = blk >> 8;
    int row0 = rt * P_ROWS;
    int tid = threadIdx.x;

    const float* E = s ? e2 : e1;
    const float* W = (mt ? Wg : Wd) + s * DDIM * KDIM;
    float* out = s ? (mt ? g_p2g : g_p2d) : (mt ? g_p1g : g_p1d);

    const float4* W4 = reinterpret_cast<const float4*>(W);
    float4* WS4 = reinterpret_cast<float4*>(WS);
    for (int i = tid; i < DDIM * KDIM / 4; i += P_THREADS) WS4[i] = W4[i];

    for (int i = tid; i < P_ROWS * (DDIM / 4); i += P_THREADS) {
        int r = i / (DDIM / 4);
        int c4 = i % (DDIM / 4);
        float4 v = *reinterpret_cast<const float4*>(&E[(size_t)(row0 + r) * DDIM + 4 * c4]);
        rowS[(4 * c4 + 0) * P_ROWS + r] = v.x;
        rowS[(4 * c4 + 1) * P_ROWS + r] = v.y;
        rowS[(4 * c4 + 2) * P_ROWS + r] = v.z;
        rowS[(4 * c4 + 3) * P_ROWS + r] = v.w;
    }
    __syncthreads();

    int k  = tid & 63;
    int r4 = tid >> 6;                   // 0..7
    if (k < KDIM) {
        float4 acc = make_float4(0.f, 0.f, 0.f, 0.f);
        #pragma unroll 4
        for (int d = 0; d < DDIM; d++) {
            float4 x = *reinterpret_cast<const float4*>(&rowS[d * P_ROWS + r4 * 4]);
            float w = WS[d * KDIM + k];
            acc.x = fmaf(x.x, w, acc.x);
            acc.y = fmaf(x.y, w, acc.y);
            acc.z = fmaf(x.z, w, acc.z);
            acc.w = fmaf(x.w, w, acc.w);
        }
        int rb = row0 + r4 * 4;
        out[(size_t)(rb + 0) * KDIM + k] = acc.x;
        out[(size_t)(rb + 1) * KDIM + k] = acc.y;
        out[(size_t)(rb + 2) * KDIM + k] = acc.z;
        out[(size_t)(rb + 3) * KDIM + k] = acc.w;
    }
}

// ---------------------------------------------------------------------------
extern "C" void kernel_launch(void* const* d_in, const int* in_sizes, int n_in,
                              void* d_out, int out_size) {
    const float* e1 = (const float*)d_in[0];
    const float* e2 = (const float*)d_in[1];
    const float* Wb = (const float*)d_in[2];
    const float* Wd = (const float*)d_in[3];
    const float* Wg = (const float*)d_in[4];
    const float* bg = (const float*)d_in[5];
    const float* bb = (const float*)d_in[6];
    const float* u  = (const float*)d_in[7];
    float* out = (float*)d_out;

    cudaFuncSetAttribute(proj_kernel, cudaFuncAttributeMaxDynamicSharedMemorySize, P_SMEM);
    cudaFuncSetAttribute(tmat_tf32_kernel, cudaFuncAttributeMaxDynamicSharedMemorySize, BT_SMEM);
    cudaFuncSetAttribute(btp_gate_kernel, cudaFuncAttributeMaxDynamicSharedMemorySize, BT_SMEM);

    convE_kernel<<<2 * ROWS1, 320>>>(e1, e2);
    convB_kernel<<<dim3(10, 10, KDIM), dim3(32, 8)>>>(Wb);
    proj_kernel<<<512, P_THREADS, P_SMEM>>>(e1, e2, Wd, Wg);
    tmat_tf32_kernel<<<dim3(ROWS1 / 128, NPAD / 128), BT_THREADS, BT_SMEM>>>();
    btp_gate_kernel<<<dim3(64, BDIM), BT_THREADS, BT_SMEM>>>(bg, bb, u, out);
}